// round 1
// baseline (speedup 1.0000x reference)
#include <cuda_runtime.h>
#include <cuda_bf16.h>

#define N_MAX 50000
#define E_MAX 800000
#define D     128

// Scratch (no allocations allowed -> __device__ globals)
__device__ int   g_deg_in[N_MAX];
__device__ int   g_deg_out[N_MAX];
__device__ int   g_row_start[N_MAX + 1];
__device__ int   g_cursor[N_MAX];
__device__ int   g_csr_src[E_MAX];
__device__ float g_norm_src[N_MAX];
__device__ float g_agg[(size_t)N_MAX * D];

// ---------------------------------------------------------------------------
// 1) zero counters
__global__ void k_init(int n) {
    int i = blockIdx.x * blockDim.x + threadIdx.x;
    if (i < n) {
        g_deg_in[i] = 0;
        g_deg_out[i] = 0;
        g_cursor[i] = 0;
    }
}

// 2) degree count
__global__ void k_count(const int* __restrict__ ei, int e) {
    int i = blockIdx.x * blockDim.x + threadIdx.x;
    if (i < e) {
        int s = ei[i];
        int d = ei[e + i];
        atomicAdd(&g_deg_out[s], 1);
        atomicAdd(&g_deg_in[d], 1);
    }
}

// 3) exclusive scan of deg_in -> row_start (single block, 1024 threads)
__global__ void k_scan(int n) {
    __shared__ int part[1024];
    int t = threadIdx.x;
    int chunk = (n + 1023) / 1024;
    int beg = t * chunk;
    int end = beg + chunk;
    if (end > n) end = n;
    int sum = 0;
    for (int i = beg; i < end; ++i) sum += g_deg_in[i];
    part[t] = sum;
    __syncthreads();
    if (t == 0) {
        int run = 0;
        for (int i = 0; i < 1024; ++i) {
            int v = part[i];
            part[i] = run;
            run += v;
        }
        g_row_start[n] = run;
    }
    __syncthreads();
    int run = part[t];
    for (int i = beg; i < end; ++i) {
        g_row_start[i] = run;
        run += g_deg_in[i];
    }
}

// 4) source-side norms
__global__ void k_norm(int n) {
    int i = blockIdx.x * blockDim.x + threadIdx.x;
    if (i < n) {
        g_norm_src[i] = rsqrtf(fmaxf((float)g_deg_out[i], 1.0f));
    }
}

// 5) fill CSR buckets (only int atomics, 1 per edge)
__global__ void k_fill(const int* __restrict__ ei, int e) {
    int i = blockIdx.x * blockDim.x + threadIdx.x;
    if (i < e) {
        int s = ei[i];
        int d = ei[e + i];
        int pos = atomicAdd(&g_cursor[d], 1);
        g_csr_src[g_row_start[d] + pos] = s;
    }
}

// 6) aggregation: one warp per destination node, float4 per lane (32*4 = 128 feats)
__global__ void k_agg(const float* __restrict__ x, int n) {
    int warp = (blockIdx.x * blockDim.x + threadIdx.x) >> 5;
    int lane = threadIdx.x & 31;
    if (warp >= n) return;

    int beg = g_row_start[warp];
    int end = g_row_start[warp + 1];

    const float4* xv = reinterpret_cast<const float4*>(x);
    float ax = 0.f, ay = 0.f, az = 0.f, aw = 0.f;

    int idx = beg;
    // 2-wide software pipeline for MLP
    for (; idx + 2 <= end; idx += 2) {
        int s0 = g_csr_src[idx];
        int s1 = g_csr_src[idx + 1];
        float n0 = g_norm_src[s0];
        float n1 = g_norm_src[s1];
        float4 v0 = xv[(size_t)s0 * 32 + lane];
        float4 v1 = xv[(size_t)s1 * 32 + lane];
        ax = fmaf(v0.x, n0, ax); ay = fmaf(v0.y, n0, ay);
        az = fmaf(v0.z, n0, az); aw = fmaf(v0.w, n0, aw);
        ax = fmaf(v1.x, n1, ax); ay = fmaf(v1.y, n1, ay);
        az = fmaf(v1.z, n1, az); aw = fmaf(v1.w, n1, aw);
    }
    if (idx < end) {
        int s0 = g_csr_src[idx];
        float n0 = g_norm_src[s0];
        float4 v0 = xv[(size_t)s0 * 32 + lane];
        ax = fmaf(v0.x, n0, ax); ay = fmaf(v0.y, n0, ay);
        az = fmaf(v0.z, n0, az); aw = fmaf(v0.w, n0, aw);
    }

    float nd = rsqrtf(fmaxf((float)g_deg_in[warp], 1.0f));
    float4 out;
    out.x = ax * nd; out.y = ay * nd; out.z = az * nd; out.w = aw * nd;
    reinterpret_cast<float4*>(g_agg)[(size_t)warp * 32 + lane] = out;
}

// 7) GEMM: out = relu(agg @ W + b). 128x128 block tile, BK=32, 8x8 micro-tile.
__global__ __launch_bounds__(256, 2) void k_gemm(const float* __restrict__ Wm,
                                                 const float* __restrict__ bias,
                                                 float* __restrict__ out, int n) {
    __shared__ float sA[128][33];   // padded to dodge bank conflicts
    __shared__ float sW[32][128];

    int tid = threadIdx.x;
    int rowBase = blockIdx.x * 128;
    int ty = tid >> 4;    // 0..15
    int tx = tid & 15;    // 0..15

    float acc[8][8];
#pragma unroll
    for (int i = 0; i < 8; ++i)
#pragma unroll
        for (int j = 0; j < 8; ++j) acc[i][j] = 0.f;

    for (int kt = 0; kt < 128; kt += 32) {
        // load A tile (128 rows x 32 k) from g_agg
#pragma unroll
        for (int i = 0; i < 4; ++i) {
            int fid = tid + i * 256;          // 0..1023
            int r = fid >> 3;                 // 0..127
            int kq = fid & 7;                 // 0..7
            int grow = rowBase + r;
            float4 v = make_float4(0.f, 0.f, 0.f, 0.f);
            if (grow < n)
                v = *reinterpret_cast<const float4*>(&g_agg[(size_t)grow * 128 + kt + kq * 4]);
            sA[r][kq * 4 + 0] = v.x;
            sA[r][kq * 4 + 1] = v.y;
            sA[r][kq * 4 + 2] = v.z;
            sA[r][kq * 4 + 3] = v.w;
        }
        // load W tile (32 k x 128 cols)
#pragma unroll
        for (int i = 0; i < 4; ++i) {
            int fid = tid + i * 256;
            int k = fid >> 5;                 // 0..31
            int cq = fid & 31;                // 0..31
            *reinterpret_cast<float4*>(&sW[k][cq * 4]) =
                *reinterpret_cast<const float4*>(&Wm[(size_t)(kt + k) * 128 + cq * 4]);
        }
        __syncthreads();

#pragma unroll
        for (int kk = 0; kk < 32; ++kk) {
            float a[8];
#pragma unroll
            for (int i = 0; i < 8; ++i) a[i] = sA[ty * 8 + i][kk];
            float4 w0 = *reinterpret_cast<const float4*>(&sW[kk][tx * 8]);
            float4 w1 = *reinterpret_cast<const float4*>(&sW[kk][tx * 8 + 4]);
            float w[8] = {w0.x, w0.y, w0.z, w0.w, w1.x, w1.y, w1.z, w1.w};
#pragma unroll
            for (int i = 0; i < 8; ++i)
#pragma unroll
                for (int j = 0; j < 8; ++j) acc[i][j] = fmaf(a[i], w[j], acc[i][j]);
        }
        __syncthreads();
    }

    float4 b0 = *reinterpret_cast<const float4*>(&bias[tx * 8]);
    float4 b1 = *reinterpret_cast<const float4*>(&bias[tx * 8 + 4]);
    float bb[8] = {b0.x, b0.y, b0.z, b0.w, b1.x, b1.y, b1.z, b1.w};

#pragma unroll
    for (int i = 0; i < 8; ++i) {
        int grow = rowBase + ty * 8 + i;
        if (grow < n) {
            float4 o0, o1;
            o0.x = fmaxf(acc[i][0] + bb[0], 0.f);
            o0.y = fmaxf(acc[i][1] + bb[1], 0.f);
            o0.z = fmaxf(acc[i][2] + bb[2], 0.f);
            o0.w = fmaxf(acc[i][3] + bb[3], 0.f);
            o1.x = fmaxf(acc[i][4] + bb[4], 0.f);
            o1.y = fmaxf(acc[i][5] + bb[5], 0.f);
            o1.z = fmaxf(acc[i][6] + bb[6], 0.f);
            o1.w = fmaxf(acc[i][7] + bb[7], 0.f);
            *reinterpret_cast<float4*>(&out[(size_t)grow * 128 + tx * 8]) = o0;
            *reinterpret_cast<float4*>(&out[(size_t)grow * 128 + tx * 8 + 4]) = o1;
        }
    }
}

extern "C" void kernel_launch(void* const* d_in, const int* in_sizes, int n_in,
                              void* d_out, int out_size) {
    const float* x   = (const float*)d_in[0];
    const int*   ei  = (const int*)d_in[1];
    const float* Wm  = (const float*)d_in[2];
    const float* bias = (const float*)d_in[3];
    float* out = (float*)d_out;

    int n = in_sizes[0] / D;       // 50000
    int e = in_sizes[1] / 2;       // 800000

    k_init<<<(n + 255) / 256, 256>>>(n);
    k_count<<<(e + 255) / 256, 256>>>(ei, e);
    k_scan<<<1, 1024>>>(n);
    k_norm<<<(n + 255) / 256, 256>>>(n);
    k_fill<<<(e + 255) / 256, 256>>>(ei, e);
    k_agg<<<(n + 7) / 8, 256>>>(x, n);
    k_gemm<<<(n + 127) / 128, 256>>>(Wm, bias, out, n);
}